// round 14
// baseline (speedup 1.0000x reference)
#include <cuda_runtime.h>
#include <math.h>

// AttFusion: out[g,c,s] = sum_m softmax_m(<x0,xm>_c / 16) * x[m,c,s]
// x: [28, 256, 8448] fp32; out: [8, 256, 8448] fp32.
//
// R14 = R11 (2-tile pipelined CTAs, templated n, __ldlu/__stwt, per-warp
// softmax, grid x=s-block / y=group) with ONE change: 128-thread CTAs at
// 6/SM (same 24 warps/SM, warp owns 64 channels = 16 chunks). More, smaller
// co-resident CTAs desynchronize the DRAM/L2/barrier phases -> higher HBM
// duty cycle; barriers couple 4 warps instead of 8.

#define C_DIM   256
#define S_DIM   8448
#define N_MAX   5
#define NWARPS  4               // 128 threads
#define NCHUNK  16              // channel chunks per warp (64 channels)
#define FULL    0xffffffffu

__device__ __constant__ int c_off[8] = {0, 2, 5, 9, 14, 17, 19, 23};
__device__ __constant__ int c_len[8] = {2, 3, 4, 5, 3, 2, 4, 5};

template <int N>
__device__ __forceinline__ void reduce_store(
    float4* p, float (*red)[NWARPS][32], int warp, int lo3, int rowg)
{
#pragma unroll
    for (int m = 0; m < N; m++) {
        p[m].x += __shfl_down_sync(FULL, p[m].x, 16);
        p[m].y += __shfl_down_sync(FULL, p[m].y, 16);
        p[m].z += __shfl_down_sync(FULL, p[m].z, 16);
        p[m].w += __shfl_down_sync(FULL, p[m].w, 16);
        p[m].x += __shfl_down_sync(FULL, p[m].x, 8);
        p[m].y += __shfl_down_sync(FULL, p[m].y, 8);
        p[m].z += __shfl_down_sync(FULL, p[m].z, 8);
        p[m].w += __shfl_down_sync(FULL, p[m].w, 8);
    }
    if (rowg == 0) {
#pragma unroll
        for (int m = 0; m < N; m++)
            *reinterpret_cast<float4*>(&red[m][warp][lo3 * 4]) = p[m];
    }
}

// per-warp redundant softmax: lane = position, then broadcast to quad lanes
template <int N>
__device__ __forceinline__ void softmax_wv(
    const float (*red)[NWARPS][32], int lane, int lo3, float4* wv)
{
    float d[N];
#pragma unroll
    for (int m = 0; m < N; m++) {
        float a = 0.0f;
#pragma unroll
        for (int w = 0; w < NWARPS; w++) a += red[m][w][lane];
        d[m] = a * 0.0625f;                    // 1/sqrt(256)
    }
    float mx = d[0];
#pragma unroll
    for (int m = 1; m < N; m++) mx = fmaxf(mx, d[m]);
    float wl[N], s = 0.0f;
#pragma unroll
    for (int m = 0; m < N; m++) { wl[m] = __expf(d[m] - mx); s += wl[m]; }
    const float inv = 1.0f / s;
#pragma unroll
    for (int m = 0; m < N; m++) {
        const float v = wl[m] * inv;
        wv[m].x = __shfl_sync(FULL, v, 4 * lo3 + 0);
        wv[m].y = __shfl_sync(FULL, v, 4 * lo3 + 1);
        wv[m].z = __shfl_sync(FULL, v, 4 * lo3 + 2);
        wv[m].w = __shfl_sync(FULL, v, 4 * lo3 + 3);
    }
}

template <int N>
__device__ __forceinline__ void run_group(
    const float* __restrict__ xg, float* __restrict__ og,
    float (*red0)[NWARPS][32], float (*red1)[NWARPS][32],
    int s0, int lane, int warp, int lo3, int rowg)
{
    const size_t mstr = (size_t)C_DIM * S_DIM;
    const size_t lpos = (size_t)(warp * 64 + rowg) * S_DIM + s0 + lo3 * 4;
    const float* xb0 = xg + lpos;
    const float* xb1 = xb0 + 32;
    float* ob0 = og + lpos;
    float* ob1 = ob0 + 32;

    // ---- P1(t0): partial dots, 16 channel chunks (DRAM) ----
    float4 p[N];
#pragma unroll
    for (int m = 0; m < N; m++) p[m] = make_float4(0.f, 0.f, 0.f, 0.f);
    {
        const float* ptr = xb0;
#pragma unroll 4
        for (int kk = 0; kk < NCHUNK; kk++) {
            float4 xv[N];
#pragma unroll
            for (int m = 0; m < N; m++)
                xv[m] = *reinterpret_cast<const float4*>(ptr + m * mstr);
#pragma unroll
            for (int m = 0; m < N; m++) {
                p[m].x += xv[0].x * xv[m].x;
                p[m].y += xv[0].y * xv[m].y;
                p[m].z += xv[0].z * xv[m].z;
                p[m].w += xv[0].w * xv[m].w;
            }
            ptr += 4 * S_DIM;
        }
    }
    reduce_store<N>(p, red0, warp, lo3, rowg);
    __syncthreads();

    // prefetch t1 chunk 0 (independent of softmax)
    float4 xn[N];
#pragma unroll
    for (int m = 0; m < N; m++)
        xn[m] = *reinterpret_cast<const float4*>(xb1 + m * mstr);

    float4 wv[N];
    softmax_wv<N>(red0, lane, lo3, wv);

    // ---- middle: P2(t0) from L2 interleaved with P1(t1) from DRAM ----
    float4 pn[N];
#pragma unroll
    for (int m = 0; m < N; m++) pn[m] = make_float4(0.f, 0.f, 0.f, 0.f);
    {
        const float* cp = xb0;
        const float* np = xb1;
        float*       op = ob0;
#pragma unroll 4
        for (int kk = 0; kk < NCHUNK; kk++) {
#pragma unroll
            for (int m = 0; m < N; m++) {
                pn[m].x += xn[0].x * xn[m].x;
                pn[m].y += xn[0].y * xn[m].y;
                pn[m].z += xn[0].z * xn[m].z;
                pn[m].w += xn[0].w * xn[m].w;
            }
            float4 xc[N];
#pragma unroll
            for (int m = 0; m < N; m++)
                xc[m] = __ldlu(reinterpret_cast<const float4*>(cp + m * mstr));
            float4 acc = make_float4(0.f, 0.f, 0.f, 0.f);
#pragma unroll
            for (int m = 0; m < N; m++) {
                acc.x += wv[m].x * xc[m].x;
                acc.y += wv[m].y * xc[m].y;
                acc.z += wv[m].z * xc[m].z;
                acc.w += wv[m].w * xc[m].w;
            }
            __stwt(reinterpret_cast<float4*>(op), acc);
            if (kk < NCHUNK - 1) {
                np += 4 * S_DIM;
#pragma unroll
                for (int m = 0; m < N; m++)
                    xn[m] = *reinterpret_cast<const float4*>(np + m * mstr);
            }
            cp += 4 * S_DIM;
            op += 4 * S_DIM;
        }
    }
    reduce_store<N>(pn, red1, warp, lo3, rowg);
    __syncthreads();
    softmax_wv<N>(red1, lane, lo3, wv);

    // ---- P2(t1): weighted sum from L2 ----
    {
        const float* ptr = xb1;
        float* op = ob1;
#pragma unroll 4
        for (int kk = 0; kk < NCHUNK; kk++) {
            float4 xc[N];
#pragma unroll
            for (int m = 0; m < N; m++)
                xc[m] = __ldlu(reinterpret_cast<const float4*>(ptr + m * mstr));
            float4 acc = make_float4(0.f, 0.f, 0.f, 0.f);
#pragma unroll
            for (int m = 0; m < N; m++) {
                acc.x += wv[m].x * xc[m].x;
                acc.y += wv[m].y * xc[m].y;
                acc.z += wv[m].z * xc[m].z;
                acc.w += wv[m].w * xc[m].w;
            }
            __stwt(reinterpret_cast<float4*>(op), acc);
            ptr += 4 * S_DIM;
            op  += 4 * S_DIM;
        }
    }
}

__global__ __launch_bounds__(128, 6)
void attfusion_kernel(const float* __restrict__ x, float* __restrict__ out) {
    __shared__ float red0[N_MAX][NWARPS][32];   // 2.5 KB
    __shared__ float red1[N_MAX][NWARPS][32];   // 2.5 KB

    const int g    = blockIdx.y;                 // same grid order as R11
    const int s0   = blockIdx.x * 64;            // two 32-pos tiles
    const int tid  = threadIdx.x;
    const int lane = tid & 31;
    const int warp = tid >> 5;
    const int lo3  = lane & 7;                   // position quad
    const int rowg = lane >> 3;                  // channel sub-row 0..3

    const size_t mstr = (size_t)C_DIM * S_DIM;
    const float* xg = x + (size_t)c_off[g] * mstr;
    float*       og = out + (size_t)g * mstr;

    switch (c_len[g]) {
        case 2: run_group<2>(xg, og, red0, red1, s0, lane, warp, lo3, rowg); break;
        case 3: run_group<3>(xg, og, red0, red1, s0, lane, warp, lo3, rowg); break;
        case 4: run_group<4>(xg, og, red0, red1, s0, lane, warp, lo3, rowg); break;
        default: run_group<5>(xg, og, red0, red1, s0, lane, warp, lo3, rowg); break;
    }
}

extern "C" void kernel_launch(void* const* d_in, const int* in_sizes, int n_in,
                              void* d_out, int out_size) {
    const float* x = (const float*)d_in[0];
    float* out = (float*)d_out;

    dim3 grid(S_DIM / 64, 8);                    // 132 x 8 = 1056 CTAs
    attfusion_kernel<<<grid, 128>>>(x, out);
}

// round 15
// speedup vs baseline: 1.2253x; 1.2253x over previous
#include <cuda_runtime.h>
#include <math.h>

// AttFusion: out[g,c,s] = sum_m softmax_m(<x0,xm>_c / 16) * x[m,c,s]
// x: [28, 256, 8448] fp32; out: [8, 256, 8448] fp32.
//
// R15 = R11's pipelined 2-tile CTA, but the two tiles come from DIFFERENT
// groups paired for constant work: chains (n=5,n=2) and (n=4,n=3) -> every
// CTA does exactly 7 agent-tiles (R11 varied 4..10). grid 264 x 4 chains =
// 1056 CTAs @3/SM = 2.38 waves, uniform -> no straggler tail.
// Everything else proven in R11 is unchanged: warp = 4 channel rows x 8
// pos-quads (4 full 128B lines per LDG.128), __ldlu pass-2 reads, __stwt
// stores, per-warp redundant softmax, one barrier per tile.

#define C_DIM   256
#define S_DIM   8448
#define N_MAX   5
#define NWARPS  8
#define FULL    0xffffffffu

template <int N>
__device__ __forceinline__ void reduce_store(
    float4* p, float (*red)[NWARPS][32], int warp, int lo3, int rowg)
{
#pragma unroll
    for (int m = 0; m < N; m++) {
        p[m].x += __shfl_down_sync(FULL, p[m].x, 16);
        p[m].y += __shfl_down_sync(FULL, p[m].y, 16);
        p[m].z += __shfl_down_sync(FULL, p[m].z, 16);
        p[m].w += __shfl_down_sync(FULL, p[m].w, 16);
        p[m].x += __shfl_down_sync(FULL, p[m].x, 8);
        p[m].y += __shfl_down_sync(FULL, p[m].y, 8);
        p[m].z += __shfl_down_sync(FULL, p[m].z, 8);
        p[m].w += __shfl_down_sync(FULL, p[m].w, 8);
    }
    if (rowg == 0) {
#pragma unroll
        for (int m = 0; m < N; m++)
            *reinterpret_cast<float4*>(&red[m][warp][lo3 * 4]) = p[m];
    }
}

// per-warp redundant softmax: lane = position, then broadcast to quad lanes
template <int N>
__device__ __forceinline__ void softmax_wv(
    const float (*red)[NWARPS][32], int lane, int lo3, float4* wv)
{
    float d[N];
#pragma unroll
    for (int m = 0; m < N; m++) {
        float a = 0.0f;
#pragma unroll
        for (int w = 0; w < NWARPS; w++) a += red[m][w][lane];
        d[m] = a * 0.0625f;                    // 1/sqrt(256)
    }
    float mx = d[0];
#pragma unroll
    for (int m = 1; m < N; m++) mx = fmaxf(mx, d[m]);
    float wl[N], s = 0.0f;
#pragma unroll
    for (int m = 0; m < N; m++) { wl[m] = __expf(d[m] - mx); s += wl[m]; }
    const float inv = 1.0f / s;
#pragma unroll
    for (int m = 0; m < N; m++) {
        const float v = wl[m] * inv;
        wv[m].x = __shfl_sync(FULL, v, 4 * lo3 + 0);
        wv[m].y = __shfl_sync(FULL, v, 4 * lo3 + 1);
        wv[m].z = __shfl_sync(FULL, v, 4 * lo3 + 2);
        wv[m].w = __shfl_sync(FULL, v, 4 * lo3 + 3);
    }
}

// Two-tile chain: tile A (group a, NA agents) then tile B (group b, NB),
// same 32-position window, pipelined exactly like R11.
template <int NA, int NB>
__device__ __forceinline__ void run_chain(
    const float* __restrict__ xa, float* __restrict__ oa,
    const float* __restrict__ xbs, float* __restrict__ ob,
    float (*red0)[NWARPS][32], float (*red1)[NWARPS][32],
    int lane, int warp, int lo3, int rowg)
{
    const size_t mstr = (size_t)C_DIM * S_DIM;

    // ---- P1(A): partial dots, 8 channel chunks (DRAM) ----
    float4 pa[NA];
#pragma unroll
    for (int m = 0; m < NA; m++) pa[m] = make_float4(0.f, 0.f, 0.f, 0.f);
    {
        const float* ptr = xa;
#pragma unroll
        for (int kk = 0; kk < 8; kk++) {
            float4 xv[NA];
#pragma unroll
            for (int m = 0; m < NA; m++)
                xv[m] = *reinterpret_cast<const float4*>(ptr + m * mstr);
#pragma unroll
            for (int m = 0; m < NA; m++) {
                pa[m].x += xv[0].x * xv[m].x;
                pa[m].y += xv[0].y * xv[m].y;
                pa[m].z += xv[0].z * xv[m].z;
                pa[m].w += xv[0].w * xv[m].w;
            }
            ptr += 4 * S_DIM;
        }
    }
    reduce_store<NA>(pa, red0, warp, lo3, rowg);
    __syncthreads();

    // prefetch B chunk 0 (independent of softmax)
    float4 xn[NB];
#pragma unroll
    for (int m = 0; m < NB; m++)
        xn[m] = *reinterpret_cast<const float4*>(xbs + m * mstr);

    float4 wva[NA];
    softmax_wv<NA>(red0, lane, lo3, wva);

    // ---- middle: P2(A) from L2 interleaved with P1(B) from DRAM ----
    float4 pb[NB];
#pragma unroll
    for (int m = 0; m < NB; m++) pb[m] = make_float4(0.f, 0.f, 0.f, 0.f);
    {
        const float* cp = xa;
        const float* np = xbs;
        float*       op = oa;
#pragma unroll
        for (int kk = 0; kk < 8; kk++) {
#pragma unroll
            for (int m = 0; m < NB; m++) {
                pb[m].x += xn[0].x * xn[m].x;
                pb[m].y += xn[0].y * xn[m].y;
                pb[m].z += xn[0].z * xn[m].z;
                pb[m].w += xn[0].w * xn[m].w;
            }
            float4 xc[NA];
#pragma unroll
            for (int m = 0; m < NA; m++)
                xc[m] = __ldlu(reinterpret_cast<const float4*>(cp + m * mstr));
            float4 acc = make_float4(0.f, 0.f, 0.f, 0.f);
#pragma unroll
            for (int m = 0; m < NA; m++) {
                acc.x += wva[m].x * xc[m].x;
                acc.y += wva[m].y * xc[m].y;
                acc.z += wva[m].z * xc[m].z;
                acc.w += wva[m].w * xc[m].w;
            }
            __stwt(reinterpret_cast<float4*>(op), acc);
            if (kk < 7) {
                np += 4 * S_DIM;
#pragma unroll
                for (int m = 0; m < NB; m++)
                    xn[m] = *reinterpret_cast<const float4*>(np + m * mstr);
            }
            cp += 4 * S_DIM;
            op += 4 * S_DIM;
        }
    }
    reduce_store<NB>(pb, red1, warp, lo3, rowg);
    __syncthreads();
    float4 wvb[NB];
    softmax_wv<NB>(red1, lane, lo3, wvb);

    // ---- P2(B): weighted sum from L2 ----
    {
        const float* ptr = xbs;
        float* op = ob;
#pragma unroll
        for (int kk = 0; kk < 8; kk++) {
            float4 xc[NB];
#pragma unroll
            for (int m = 0; m < NB; m++)
                xc[m] = __ldlu(reinterpret_cast<const float4*>(ptr + m * mstr));
            float4 acc = make_float4(0.f, 0.f, 0.f, 0.f);
#pragma unroll
            for (int m = 0; m < NB; m++) {
                acc.x += wvb[m].x * xc[m].x;
                acc.y += wvb[m].y * xc[m].y;
                acc.z += wvb[m].z * xc[m].z;
                acc.w += wvb[m].w * xc[m].w;
            }
            __stwt(reinterpret_cast<float4*>(op), acc);
            ptr += 4 * S_DIM;
            op  += 4 * S_DIM;
        }
    }
}

// chains: (xoffA, goutA, xoffB, goutB) with (nA,nB) = (5,2),(5,2),(4,3),(4,3)
__device__ __constant__ int ch_offA[4] = {9, 23, 5, 19};
__device__ __constant__ int ch_gA[4]   = {3,  7, 2,  6};
__device__ __constant__ int ch_offB[4] = {0, 17, 2, 14};
__device__ __constant__ int ch_gB[4]   = {0,  5, 1,  4};

__global__ __launch_bounds__(256, 3)
void attfusion_kernel(const float* __restrict__ x, float* __restrict__ out) {
    __shared__ float red0[N_MAX][NWARPS][32];   // 5 KB
    __shared__ float red1[N_MAX][NWARPS][32];   // 5 KB

    const int ch   = blockIdx.y;                 // chain 0..3
    const int s0   = blockIdx.x * 32;            // one 32-pos window
    const int tid  = threadIdx.x;
    const int lane = tid & 31;
    const int warp = tid >> 5;
    const int lo3  = lane & 7;                   // position quad
    const int rowg = lane >> 3;                  // channel sub-row 0..3

    const size_t mstr = (size_t)C_DIM * S_DIM;
    const size_t lpos = (size_t)(warp * 32 + rowg) * S_DIM + s0 + lo3 * 4;

    const float* xa = x   + (size_t)ch_offA[ch] * mstr + lpos;
    float*       oa = out + (size_t)ch_gA[ch]   * mstr + lpos;
    const float* xb = x   + (size_t)ch_offB[ch] * mstr + lpos;
    float*       ob = out + (size_t)ch_gB[ch]   * mstr + lpos;

    if (ch < 2)
        run_chain<5, 2>(xa, oa, xb, ob, red0, red1, lane, warp, lo3, rowg);
    else
        run_chain<4, 3>(xa, oa, xb, ob, red0, red1, lane, warp, lo3, rowg);
}

extern "C" void kernel_launch(void* const* d_in, const int* in_sizes, int n_in,
                              void* d_out, int out_size) {
    const float* x = (const float*)d_in[0];
    float* out = (float*)d_out;

    dim3 grid(S_DIM / 32, 4);                    // 264 x 4 = 1056 CTAs
    attfusion_kernel<<<grid, 256>>>(x, out);
}